// round 13
// baseline (speedup 1.0000x reference)
#include <cuda_runtime.h>
#include <cuda_fp16.h>
#include <cstdint>

#define NN   100000
#define NE   1600000
#define DIN  128
#define DH   256
#define NCLS 32

typedef unsigned long long ull;

// ---------------- scratch (device globals; zero-init at load) ---------------
// g_deg/g_cursor/g_stats are re-zeroed by tail kernels each run so the next
// graph replay sees clean state (zero-init covers the first run).
__device__ int   g_deg[NN];
__device__ int   g_rowptr[NN + 1];
__device__ int   g_cursor[NN];
__device__ int   g_csr[NE];
__device__ int   g_bsum[128];
__device__ __align__(128) __half g_Ahi[(size_t)NN * DH];
__device__ __align__(128) __half g_Shi[(size_t)NN * DH];
__device__ __align__(128) __half g_Bl1[DH * DIN];   // W1l pack [256 n][128 k]
__device__ __align__(128) __half g_Br1[DH * DIN];   // W1r pack
__device__ __align__(128) __half g_Bl2[DH * DH];    // W2l pack [256 n][256 k]
__device__ __align__(128) __half g_Br2[DH * DH];    // W2r pack
__device__ __align__(128) float  g_h1[(size_t)NN * DH];
__device__ __align__(128) float  g_h2[(size_t)NN * DH];
__device__ float g_stats[1024];

// ---------------- helpers ---------------------------------------------------
__device__ __forceinline__ uint32_t smem_u32(const void* p) {
    uint32_t a;
    asm("{ .reg .u64 t; cvta.to.shared.u64 t, %1; cvt.u32.u64 %0, t; }"
        : "=r"(a) : "l"(p));
    return a;
}
__device__ __forceinline__ void cpasync16(uint32_t dst, const void* src) {
    asm volatile("cp.async.cg.shared.global [%0], [%1], 16;"
                 :: "r"(dst), "l"(src));
}
#define CP_COMMIT() asm volatile("cp.async.commit_group;" ::: "memory")

__device__ __forceinline__ void ldsm_x4(uint32_t* r, uint32_t addr) {
    asm volatile("ldmatrix.sync.aligned.m8n8.x4.shared.b16 {%0,%1,%2,%3}, [%4];"
                 : "=r"(r[0]), "=r"(r[1]), "=r"(r[2]), "=r"(r[3]) : "r"(addr));
}
__device__ __forceinline__ void mma16816(float* c, const uint32_t* a,
                                         const uint32_t* b) {
    asm volatile(
        "mma.sync.aligned.m16n8k16.row.col.f32.f16.f16.f32 "
        "{%0,%1,%2,%3}, {%4,%5,%6,%7}, {%8,%9}, {%0,%1,%2,%3};"
        : "+f"(c[0]), "+f"(c[1]), "+f"(c[2]), "+f"(c[3])
        : "r"(a[0]), "r"(a[1]), "r"(a[2]), "r"(a[3]), "r"(b[0]), "r"(b[1]));
}

__device__ __forceinline__ uint32_t pkh(float a, float b) {
    __half2 t = __floats2half2_rn(a, b);
    return *(uint32_t*)&t;
}

// ---------------- scan helper ----------------------------------------------
__device__ __forceinline__ int block_scan_incl(int v) {
    __shared__ int ws[32];
    int lane = threadIdx.x & 31, wid = threadIdx.x >> 5;
#pragma unroll
    for (int o = 1; o < 32; o <<= 1) {
        int n = __shfl_up_sync(0xffffffffu, v, o);
        if (lane >= o) v += n;
    }
    if (lane == 31) ws[wid] = v;
    __syncthreads();
    int nw = blockDim.x >> 5;
    if (wid == 0) {
        int s = (lane < nw) ? ws[lane] : 0;
#pragma unroll
        for (int o = 1; o < 32; o <<= 1) {
            int n = __shfl_up_sync(0xffffffffu, s, o);
            if (lane >= o) s += n;
        }
        ws[lane] = s;
    }
    __syncthreads();
    if (wid > 0) v += ws[wid - 1];
    return v;
}

// ---------------- fused prep1: hist | x-split | prepB(4 packs) --------------
// blocks [0,1563): hist; [1563,2587): split; [2587,2715): prepB layer1;
// [2715,2971): prepB layer2.  g_deg zeroed by previous run's k_fc.
__global__ void __launch_bounds__(256) k_prep1(
    const int* __restrict__ dst, const float* __restrict__ X,
    __half* __restrict__ Shi,
    const float* __restrict__ W1l, const float* __restrict__ W1r,
    __half* __restrict__ Bl1, __half* __restrict__ Br1,
    const float* __restrict__ W2l, const float* __restrict__ W2r,
    __half* __restrict__ Bl2, __half* __restrict__ Br2) {
    int b = blockIdx.x, t = threadIdx.x;
    if (b < 1563) {
        int e4 = b * 256 + t;
        if (e4 * 4 < NE) {
            int4 d = __ldg((const int4*)dst + e4);
            atomicAdd(&g_deg[d.x], 1);
            atomicAdd(&g_deg[d.y], 1);
            atomicAdd(&g_deg[d.z], 1);
            atomicAdd(&g_deg[d.w], 1);
        }
    } else if (b < 2587) {
        const int total4 = NN * DIN / 4;
        for (int i = (b - 1563) * 256 + t; i < total4; i += 1024 * 256) {
            float4 v = ((const float4*)X)[i];
            uint2 h = make_uint2(pkh(v.x, v.y), pkh(v.z, v.w));
            *(uint2*)((char*)Shi + (size_t)i * 8) = h;
        }
    } else if (b < 2715) {
        int idx = (b - 2587) * 256 + t;          // DIN*256 elements
        int k = idx >> 8, n = idx & 255;
        Bl1[(size_t)n * DIN + k] = __float2half_rn(W1l[idx]);
        Br1[(size_t)n * DIN + k] = __float2half_rn(W1r[idx]);
    } else {
        int idx = (b - 2715) * 256 + t;          // DH*256 elements
        int k = idx >> 8, n = idx & 255;
        Bl2[(size_t)n * DH + k] = __float2half_rn(W2l[idx]);
        Br2[(size_t)n * DH + k] = __float2half_rn(W2r[idx]);
    }
}

// ---------------- CSR scan + fill ------------------------------------------
__global__ void k_scan1() {
    int i = blockIdx.x * 1024 + threadIdx.x;
    int v = (i < NN) ? g_deg[i] : 0;
    int incl = block_scan_incl(v);
    if (i < NN) g_rowptr[i + 1] = incl;
    if (threadIdx.x == 1023) g_bsum[blockIdx.x] = incl;
}
__global__ void k_scan3(int nb) {
    __shared__ int s_off;
    int t = threadIdx.x;
    int v = (t < nb) ? g_bsum[t] : 0;
    int incl = block_scan_incl(v);
    if (blockIdx.x == 0) {
        if (t == 0) s_off = 0;
    } else if (t == (int)blockIdx.x - 1) {
        s_off = incl;
    }
    __syncthreads();
    int i = blockIdx.x * 1024 + t;
    if (i < NN) g_rowptr[i + 1] += s_off;
    if (i == 0) g_rowptr[0] = 0;
}
__global__ void k_fill(const int* __restrict__ src, const int* __restrict__ dst) {
    int e4 = blockIdx.x * blockDim.x + threadIdx.x;
    if (e4 * 4 < NE) {
        int4 d = __ldg((const int4*)dst + e4);
        int4 s = __ldg((const int4*)src + e4);
        int p;
        p = atomicAdd(&g_cursor[d.x], 1); g_csr[g_rowptr[d.x] + p] = s.x;
        p = atomicAdd(&g_cursor[d.y], 1); g_csr[g_rowptr[d.y] + p] = s.y;
        p = atomicAdd(&g_cursor[d.z], 1); g_csr[g_rowptr[d.z] + p] = s.z;
        p = atomicAdd(&g_cursor[d.w], 1); g_csr[g_rowptr[d.w] + p] = s.w;
    }
}

// ---------------- SpMM layer1: gather fp16 table (D=128) -------------------
__global__ void __launch_bounds__(256) k_spmm1(const __half* __restrict__ Xh,
                                               __half* __restrict__ Ahi) {
    int warp = threadIdx.x >> 5, lane = threadIdx.x & 31;
    int node = blockIdx.x * 8 + warp;
    if (node >= NN) return;
    int beg = g_rowptr[node], end = g_rowptr[node + 1];
    int deg = end - beg;
    int myidx = (beg + lane < end) ? __ldg(&g_csr[beg + lane]) : 0;
    int dmax = deg < 32 ? deg : 32;

    float4 p = make_float4(0.f, 0.f, 0.f, 0.f);
    float4 q = make_float4(0.f, 0.f, 0.f, 0.f);

    auto addu2 = [&](float4& a, uint2 u) {
        __half2* ph = (__half2*)&u;
        float2 f0 = __half22float2(ph[0]);
        float2 f1 = __half22float2(ph[1]);
        a.x += f0.x; a.y += f0.y; a.z += f1.x; a.w += f1.y;
    };

    int j = 0;
    for (; j + 4 <= dmax; j += 4) {
        int s0 = __shfl_sync(0xffffffffu, myidx, j + 0);
        int s1 = __shfl_sync(0xffffffffu, myidx, j + 1);
        int s2 = __shfl_sync(0xffffffffu, myidx, j + 2);
        int s3 = __shfl_sync(0xffffffffu, myidx, j + 3);
        uint2 u0 = __ldg((const uint2*)(Xh + (size_t)s0 * DIN) + lane);
        uint2 u1 = __ldg((const uint2*)(Xh + (size_t)s1 * DIN) + lane);
        uint2 u2 = __ldg((const uint2*)(Xh + (size_t)s2 * DIN) + lane);
        uint2 u3 = __ldg((const uint2*)(Xh + (size_t)s3 * DIN) + lane);
        addu2(p, u0); addu2(q, u1); addu2(p, u2); addu2(q, u3);
    }
    for (; j < dmax; j++) {
        int s0 = __shfl_sync(0xffffffffu, myidx, j);
        addu2(p, __ldg((const uint2*)(Xh + (size_t)s0 * DIN) + lane));
    }
    for (int jj = beg + 32; jj < end; jj++) {
        int s0 = __ldg(&g_csr[jj]);
        addu2(p, __ldg((const uint2*)(Xh + (size_t)s0 * DIN) + lane));
    }

    float inv = 1.f / fmaxf((float)deg, 1.f);
    float4 a = make_float4((p.x + q.x) * inv, (p.y + q.y) * inv,
                           (p.z + q.z) * inv, (p.w + q.w) * inv);
    uint2 h = make_uint2(pkh(a.x, a.y), pkh(a.z, a.w));
    *(uint2*)(Ahi + (size_t)node * DIN + lane * 4) = h;
}

// ---------------- SpMM layer2: gather fp16 table (D=256) -------------------
__global__ void __launch_bounds__(256) k_spmm2(const __half* __restrict__ Xh,
                                               __half* __restrict__ Ahi) {
    int warp = threadIdx.x >> 5, lane = threadIdx.x & 31;
    int node = blockIdx.x * 8 + warp;
    if (node >= NN) return;
    int beg = g_rowptr[node], end = g_rowptr[node + 1];
    int deg = end - beg;
    int myidx = (beg + lane < end) ? __ldg(&g_csr[beg + lane]) : 0;
    int dmax = deg < 32 ? deg : 32;

    float p[8] = {0, 0, 0, 0, 0, 0, 0, 0};
    float q[8] = {0, 0, 0, 0, 0, 0, 0, 0};

    auto addu4 = [&](float* a, uint4 u) {
        __half2* ph = (__half2*)&u;
#pragma unroll
        for (int z = 0; z < 4; z++) {
            float2 f = __half22float2(ph[z]);
            a[z * 2] += f.x; a[z * 2 + 1] += f.y;
        }
    };

    int j = 0;
    for (; j + 2 <= dmax; j += 2) {
        int s0 = __shfl_sync(0xffffffffu, myidx, j + 0);
        int s1 = __shfl_sync(0xffffffffu, myidx, j + 1);
        uint4 u0 = __ldg((const uint4*)(Xh + (size_t)s0 * DH) + lane);
        uint4 u1 = __ldg((const uint4*)(Xh + (size_t)s1 * DH) + lane);
        addu4(p, u0); addu4(q, u1);
    }
    for (; j < dmax; j++) {
        int s0 = __shfl_sync(0xffffffffu, myidx, j);
        addu4(p, __ldg((const uint4*)(Xh + (size_t)s0 * DH) + lane));
    }
    for (int jj = beg + 32; jj < end; jj++) {
        int s0 = __ldg(&g_csr[jj]);
        addu4(p, __ldg((const uint4*)(Xh + (size_t)s0 * DH) + lane));
    }

    float inv = 1.f / fmaxf((float)deg, 1.f);
    uint4 h;
    uint32_t* hp = (uint32_t*)&h;
#pragma unroll
    for (int z = 0; z < 4; z++) {
        float v0 = (p[z * 2] + q[z * 2]) * inv;
        float v1 = (p[z * 2 + 1] + q[z * 2 + 1]) * inv;
        hp[z] = pkh(v0, v1);
    }
    *(uint4*)(Ahi + (size_t)node * DH + lane * 8) = h;
}

// ---------------- single-product mma.sync GEMM ------------------------------
// Out = A@B (ADD=false), or Out += A@B + bias with BN stats (ADD=true).
// CTA 128x128, K-chunk 64, up to 3 stages x 32KB.
template <int K, bool ADD>
__global__ void __launch_bounds__(256, 2)
k_gemm(const __half* __restrict__ A, const __half* __restrict__ Bh,
       const float* __restrict__ bias, float* __restrict__ Out,
       float* __restrict__ stats) {
    constexpr int CH  = K / 64;
    constexpr int NST = (CH < 3) ? CH : 3;
    constexpr int T_BH = 16384;
    constexpr int STAGE = 32768;

    extern __shared__ __align__(128) char dsm[];
    float* sbias = (float*)dsm;                 // 512B
    float* s_red = (float*)(dsm + 512);         // 1KB
    uint32_t stage0 = smem_u32(dsm) + 2048;

    const int t = threadIdx.x;
    const int wid = t >> 5, lane = t & 31;
    const int wm = wid >> 2, wn = wid & 3;       // warps 2 x 4
    const int m0 = blockIdx.x * 128;
    const int n0 = blockIdx.y * 128;

    if (ADD && t < 128) {
        sbias[t] = bias[n0 + t];
        s_red[t] = 0.f; s_red[128 + t] = 0.f;
    }

    float acc[4][4][4];
#pragma unroll
    for (int i = 0; i < 4; i++)
#pragma unroll
        for (int j = 0; j < 4; j++)
#pragma unroll
            for (int q = 0; q < 4; q++) acc[i][j][q] = 0.f;

    auto load_chunk = [&](int c, int s) {
        uint32_t sb = stage0 + s * STAGE;
        int k0 = c * 64;
#pragma unroll
        for (int it = 0; it < 4; it++) {
            int i = t + 256 * it;                 // 0..1023
            int row = i >> 3, ch = i & 7;
            uint32_t sw = row * 128 + ((ch ^ (row & 7)) << 4);
            int gr = m0 + row; if (gr > NN - 1) gr = NN - 1;
            cpasync16(sb + sw, A + (size_t)gr * K + k0 + ch * 8);
            cpasync16(sb + T_BH + sw, Bh + (size_t)(n0 + row) * K + k0 + ch * 8);
        }
        CP_COMMIT();
    };

    load_chunk(0, 0);
    if (CH > 1) load_chunk(1, 1);
    if (CH > 2) load_chunk(2, 2);

#pragma unroll 1
    for (int c = 0; c < CH; c++) {
        int s = c % NST;
        int rem = CH - 1 - c;
        if (rem >= 2 && NST > 2) asm volatile("cp.async.wait_group 2;" ::: "memory");
        else if (rem >= 1)       asm volatile("cp.async.wait_group 1;" ::: "memory");
        else                     asm volatile("cp.async.wait_group 0;" ::: "memory");
        __syncthreads();

        uint32_t sb = stage0 + s * STAGE;
#pragma unroll
        for (int ks = 0; ks < 4; ks++) {
            uint32_t aH[4][4], bH[4][2];
#pragma unroll
            for (int mt = 0; mt < 4; mt++) {
                int r = wm * 64 + mt * 16 + (lane & 15);
                int kc = ks * 2 + (lane >> 4);
                ldsm_x4(aH[mt], sb + r * 128 + ((kc ^ (r & 7)) << 4));
            }
#pragma unroll
            for (int np = 0; np < 2; np++) {
                int nrow = wn * 32 + np * 16 + (lane & 7) + ((lane >> 4) << 3);
                int kc = ks * 2 + ((lane >> 3) & 1);
                uint32_t bp[4];
                ldsm_x4(bp, sb + T_BH + nrow * 128 + ((kc ^ (nrow & 7)) << 4));
                bH[np * 2][0] = bp[0];     bH[np * 2][1] = bp[1];
                bH[np * 2 + 1][0] = bp[2]; bH[np * 2 + 1][1] = bp[3];
            }
#pragma unroll
            for (int mt = 0; mt < 4; mt++)
#pragma unroll
                for (int nt = 0; nt < 4; nt++)
                    mma16816(acc[mt][nt], aH[mt], bH[nt]);
        }
        __syncthreads();
        if (c + NST < CH) load_chunk(c + NST, s);
    }

    // epilogue
    if (!ADD) {
#pragma unroll
        for (int mt = 0; mt < 4; mt++) {
            int r0 = m0 + wm * 64 + mt * 16 + (lane >> 2);
#pragma unroll
            for (int nt = 0; nt < 4; nt++) {
                int lc = wn * 32 + nt * 8 + (lane & 3) * 2;
                if (r0 < NN)
                    *(float2*)(Out + (size_t)r0 * DH + n0 + lc) =
                        make_float2(acc[mt][nt][0], acc[mt][nt][1]);
                if (r0 + 8 < NN)
                    *(float2*)(Out + (size_t)(r0 + 8) * DH + n0 + lc) =
                        make_float2(acc[mt][nt][2], acc[mt][nt][3]);
            }
        }
        return;
    }

    // ADD: read prior (self product), add bias, store, BN stats
    float csum[4][2], csq[4][2];
#pragma unroll
    for (int nt = 0; nt < 4; nt++) {
        csum[nt][0] = 0.f; csum[nt][1] = 0.f;
        csq[nt][0] = 0.f;  csq[nt][1] = 0.f;
    }
#pragma unroll
    for (int mt = 0; mt < 4; mt++) {
        int r0 = m0 + wm * 64 + mt * 16 + (lane >> 2);
        bool v0ok = r0 < NN, v1ok = (r0 + 8) < NN;
#pragma unroll
        for (int nt = 0; nt < 4; nt++) {
            int lc = wn * 32 + nt * 8 + (lane & 3) * 2;
            float bx = sbias[lc], by = sbias[lc + 1];
            if (v0ok) {
                float2 old = *(float2*)(Out + (size_t)r0 * DH + n0 + lc);
                float vx = acc[mt][nt][0] + old.x + bx;
                float vy = acc[mt][nt][1] + old.y + by;
                *(float2*)(Out + (size_t)r0 * DH + n0 + lc) = make_float2(vx, vy);
                csum[nt][0] += vx; csq[nt][0] += vx * vx;
                csum[nt][1] += vy; csq[nt][1] += vy * vy;
            }
            if (v1ok) {
                float2 old = *(float2*)(Out + (size_t)(r0 + 8) * DH + n0 + lc);
                float vx = acc[mt][nt][2] + old.x + bx;
                float vy = acc[mt][nt][3] + old.y + by;
                *(float2*)(Out + (size_t)(r0 + 8) * DH + n0 + lc) = make_float2(vx, vy);
                csum[nt][0] += vx; csq[nt][0] += vx * vx;
                csum[nt][1] += vy; csq[nt][1] += vy * vy;
            }
        }
    }
#pragma unroll
    for (int nt = 0; nt < 4; nt++) {
#pragma unroll
        for (int off = 4; off < 32; off <<= 1) {
            csum[nt][0] += __shfl_xor_sync(0xffffffffu, csum[nt][0], off);
            csum[nt][1] += __shfl_xor_sync(0xffffffffu, csum[nt][1], off);
            csq[nt][0]  += __shfl_xor_sync(0xffffffffu, csq[nt][0], off);
            csq[nt][1]  += __shfl_xor_sync(0xffffffffu, csq[nt][1], off);
        }
    }
    __syncthreads();
    if (lane < 4) {
#pragma unroll
        for (int nt = 0; nt < 4; nt++) {
            int lc = wn * 32 + nt * 8 + lane * 2;
            atomicAdd(&s_red[lc], csum[nt][0]);
            atomicAdd(&s_red[lc + 1], csum[nt][1]);
            atomicAdd(&s_red[128 + lc], csq[nt][0]);
            atomicAdd(&s_red[128 + lc + 1], csq[nt][1]);
        }
    }
    __syncthreads();
    if (t < 128) {
        atomicAdd(&stats[n0 + t], s_red[t]);
        atomicAdd(&stats[256 + n0 + t], s_red[128 + t]);
    }
}

// ---------------- prep2: BN+ReLU->fp16 + zero layer2 stats ------------------
__global__ void __launch_bounds__(256) k_prep2(const float* __restrict__ H,
                                               const float* __restrict__ stats,
                                               const float* __restrict__ gam,
                                               const float* __restrict__ bet,
                                               __half* __restrict__ Hi,
                                               float* __restrict__ stats_mut) {
    int b = blockIdx.x, t = threadIdx.x;
    if (b >= 1024) {
        stats_mut[512 + t] = 0.f;
        stats_mut[768 + t] = 0.f;
        return;
    }
    __shared__ float sbn[512];
    {
        int c = t;
        float mu  = stats[c] * (1.f / NN);
        float var = stats[256 + c] * (1.f / NN) - mu * mu;
        float rstd = rsqrtf(var + 1e-5f);
        float sc = rstd * gam[c];
        sbn[c] = sc;
        sbn[256 + c] = bet[c] - mu * sc;
    }
    __syncthreads();
    const int total = NN * DH / 4;
    for (int i = b * 256 + t; i < total; i += 1024 * 256) {
        float4 v = ((const float4*)H)[i];
        int c = (i & 63) * 4;
        v.x = fmaxf(0.f, v.x * sbn[c + 0] + sbn[256 + c + 0]);
        v.y = fmaxf(0.f, v.y * sbn[c + 1] + sbn[256 + c + 1]);
        v.z = fmaxf(0.f, v.z * sbn[c + 2] + sbn[256 + c + 2]);
        v.w = fmaxf(0.f, v.w * sbn[c + 3] + sbn[256 + c + 3]);
        uint2 h = make_uint2(pkh(v.x, v.y), pkh(v.z, v.w));
        *(uint2*)((char*)Hi + (size_t)i * 8) = h;
    }
}

// ---------------- final FC (BN fused) + re-zero state for next replay -------
__global__ void __launch_bounds__(256) k_fc(const float* __restrict__ H,
                                            float* __restrict__ stats,
                                            const float* __restrict__ gam,
                                            const float* __restrict__ bet,
                                            const float* __restrict__ W,
                                            const float* __restrict__ b,
                                            float* __restrict__ out) {
    int blk = blockIdx.x, t = threadIdx.x;
    if (blk >= 3125) {
        int i = (blk - 3125) * 256 + t;
        if (i < NN) { g_deg[i] = 0; g_cursor[i] = 0; }
        if (i < 512) stats[i] = 0.f;
        return;
    }
    __shared__ __align__(16) float Ws[DH * NCLS];
    __shared__ float sbn[512];
    for (int i = t; i < DH * NCLS / 4; i += 256)
        ((float4*)Ws)[i] = ((const float4*)W)[i];
    {
        int c = t;
        float mu  = stats[512 + c] * (1.f / NN);
        float var = stats[768 + c] * (1.f / NN) - mu * mu;
        float rstd = rsqrtf(var + 1e-5f);
        float sc = rstd * gam[c];
        sbn[c] = sc;
        sbn[256 + c] = bet[c] - mu * sc;
    }
    __syncthreads();
    int row = blk * 32 + (t >> 3);
    int c = (t & 7) * 4;
    if (row >= NN) return;
    const float4* hr = (const float4*)(H + (size_t)row * DH);
    float4 acc = *(const float4*)(b + c);
#pragma unroll 8
    for (int k4 = 0; k4 < DH / 4; k4++) {
        float4 h = hr[k4];
        int kb = k4 * 4;
        h.x = fmaxf(0.f, h.x * sbn[kb + 0] + sbn[256 + kb + 0]);
        h.y = fmaxf(0.f, h.y * sbn[kb + 1] + sbn[256 + kb + 1]);
        h.z = fmaxf(0.f, h.z * sbn[kb + 2] + sbn[256 + kb + 2]);
        h.w = fmaxf(0.f, h.w * sbn[kb + 3] + sbn[256 + kb + 3]);
        float4 w0 = *(float4*)&Ws[(kb + 0) * NCLS + c];
        float4 w1 = *(float4*)&Ws[(kb + 1) * NCLS + c];
        float4 w2 = *(float4*)&Ws[(kb + 2) * NCLS + c];
        float4 w3 = *(float4*)&Ws[(kb + 3) * NCLS + c];
        acc.x += h.x * w0.x + h.y * w1.x + h.z * w2.x + h.w * w3.x;
        acc.y += h.x * w0.y + h.y * w1.y + h.z * w2.y + h.w * w3.y;
        acc.z += h.x * w0.z + h.y * w1.z + h.z * w2.z + h.w * w3.z;
        acc.w += h.x * w0.w + h.y * w1.w + h.z * w2.w + h.w * w3.w;
    }
    *(float4*)(out + (size_t)row * NCLS + c) = acc;
}

// ---------------- launch ----------------------------------------------------
extern "C" void kernel_launch(void* const* d_in, const int* in_sizes, int n_in,
                              void* d_out, int out_size) {
    const float* x    = (const float*)d_in[0];
    const int*   esrc = (const int*)d_in[1];
    const int*   edst = (const int*)d_in[2];
    const float* W1l  = (const float*)d_in[3];
    const float* b1   = (const float*)d_in[4];
    const float* W1r  = (const float*)d_in[5];
    const float* g1   = (const float*)d_in[6];
    const float* be1  = (const float*)d_in[7];
    const float* W2l  = (const float*)d_in[8];
    const float* b2   = (const float*)d_in[9];
    const float* W2r  = (const float*)d_in[10];
    const float* g2   = (const float*)d_in[11];
    const float* be2  = (const float*)d_in[12];
    const float* Wfc  = (const float*)d_in[13];
    const float* bfc  = (const float*)d_in[14];
    float* out = (float*)d_out;

    __half *p_Ahi, *p_Shi, *p_Bl1, *p_Br1, *p_Bl2, *p_Br2;
    float *p_h1, *p_h2, *p_stats;
    cudaGetSymbolAddress((void**)&p_Ahi,   g_Ahi);
    cudaGetSymbolAddress((void**)&p_Shi,   g_Shi);
    cudaGetSymbolAddress((void**)&p_Bl1,   g_Bl1);
    cudaGetSymbolAddress((void**)&p_Br1,   g_Br1);
    cudaGetSymbolAddress((void**)&p_Bl2,   g_Bl2);
    cudaGetSymbolAddress((void**)&p_Br2,   g_Br2);
    cudaGetSymbolAddress((void**)&p_h1,    g_h1);
    cudaGetSymbolAddress((void**)&p_h2,    g_h2);
    cudaGetSymbolAddress((void**)&p_stats, g_stats);

    // second stream + events, created once (host-side objects only)
    static cudaStream_t s2 = nullptr;
    static cudaEvent_t evA = nullptr, evB = nullptr, evC = nullptr, evD = nullptr;
    if (s2 == nullptr) {
        cudaStreamCreateWithFlags(&s2, cudaStreamNonBlocking);
        cudaEventCreateWithFlags(&evA, cudaEventDisableTiming);
        cudaEventCreateWithFlags(&evB, cudaEventDisableTiming);
        cudaEventCreateWithFlags(&evC, cudaEventDisableTiming);
        cudaEventCreateWithFlags(&evD, cudaEventDisableTiming);
    }

    const int SMEM = 2048 + 3 * 32768;   // 100352
    cudaFuncSetAttribute(k_gemm<DIN, false>,
                         cudaFuncAttributeMaxDynamicSharedMemorySize, SMEM);
    cudaFuncSetAttribute(k_gemm<DIN, true>,
                         cudaFuncAttributeMaxDynamicSharedMemorySize, SMEM);
    cudaFuncSetAttribute(k_gemm<DH, false>,
                         cudaFuncAttributeMaxDynamicSharedMemorySize, SMEM);
    cudaFuncSetAttribute(k_gemm<DH, true>,
                         cudaFuncAttributeMaxDynamicSharedMemorySize, SMEM);

    const int nb1 = (NN + 1023) / 1024;
    const int e4grid = (NE / 4 + 255) / 256;
    dim3 gg((NN + 127) / 128, 2);        // 782 x 2 CTAs

    // prep (hist | split | prepB), then fork self-product onto s2
    k_prep1<<<2971, 256>>>(edst, x, p_Shi, W1l, W1r, p_Bl1, p_Br1,
                           W2l, W2r, p_Bl2, p_Br2);
    cudaEventRecord(evA, 0);
    cudaStreamWaitEvent(s2, evA, 0);
    k_gemm<DIN, false><<<gg, 256, SMEM, s2>>>(p_Shi, p_Br1, nullptr, p_h1, nullptr);
    cudaEventRecord(evB, s2);

    // main stream: CSR build + aggregation
    k_scan1<<<nb1, 1024>>>();
    k_scan3<<<nb1, 1024>>>(nb1);
    k_fill<<<e4grid, 256>>>(esrc, edst);
    k_spmm1<<<(NN + 7) / 8, 256>>>(p_Shi, p_Ahi);

    // join: agg product accumulates into h1, bias + BN stats
    cudaStreamWaitEvent(0, evB, 0);
    k_gemm<DIN, true><<<gg, 256, SMEM>>>(p_Ahi, p_Bl1, b1, p_h1, p_stats);

    // bnrelu (+ zero layer2 stats), then fork layer-2 self product
    k_prep2<<<1025, 256>>>(p_h1, p_stats, g1, be1, p_Shi, p_stats);
    cudaEventRecord(evC, 0);
    cudaStreamWaitEvent(s2, evC, 0);
    k_gemm<DH, false><<<gg, 256, SMEM, s2>>>(p_Shi, p_Br2, nullptr, p_h2, nullptr);
    cudaEventRecord(evD, s2);

    // main stream: layer-2 aggregation
    k_spmm2<<<(NN + 7) / 8, 256>>>(p_Shi, p_Ahi);

    // join: agg product into h2 + stats
    cudaStreamWaitEvent(0, evD, 0);
    k_gemm<DH, true><<<gg, 256, SMEM>>>(p_Ahi, p_Bl2, b2, p_h2, p_stats + 512);

    // classifier + re-zero deg/cursor/layer1-stats for next replay
    k_fc<<<3516, 256>>>(p_h2, p_stats, g2, be2, Wfc, bfc, out);
}

// round 14
// speedup vs baseline: 1.2799x; 1.2799x over previous
#include <cuda_runtime.h>
#include <cuda_fp16.h>
#include <cstdint>

#define NN   100000
#define NE   1600000
#define DIN  128
#define DH   256
#define NCLS 32

typedef unsigned long long ull;

// ---------------- scratch (device globals; zero-init at load) ---------------
// g_deg/g_cursor/g_stats are re-zeroed by tail kernels each run so the next
// graph replay sees clean state (zero-init covers the first run).
__device__ int   g_deg[NN];
__device__ int   g_rowptr[NN + 1];
__device__ int   g_cursor[NN];
__device__ int   g_csr[NE];
__device__ int   g_bsum[128];
__device__ __align__(128) __half g_Ahi[(size_t)NN * DH];
__device__ __align__(128) __half g_Shi[(size_t)NN * DH];
__device__ __align__(128) __half g_Bhi[DIN * 2 * DH];    // layer1 B: 256 x 256
__device__ __align__(128) __half g_Bhi2[DH * 2 * DH];    // layer2 B: 256 x 512
__device__ __align__(128) __half g_h1[(size_t)NN * DH];  // fp16 hidden states
__device__ __align__(128) __half g_h2[(size_t)NN * DH];
__device__ float g_stats[1024];

// ---------------- helpers ---------------------------------------------------
__device__ __forceinline__ uint32_t smem_u32(const void* p) {
    uint32_t a;
    asm("{ .reg .u64 t; cvta.to.shared.u64 t, %1; cvt.u32.u64 %0, t; }"
        : "=r"(a) : "l"(p));
    return a;
}
__device__ __forceinline__ void cpasync16(uint32_t dst, const void* src) {
    asm volatile("cp.async.cg.shared.global [%0], [%1], 16;"
                 :: "r"(dst), "l"(src));
}
#define CP_COMMIT() asm volatile("cp.async.commit_group;" ::: "memory")

__device__ __forceinline__ void ldsm_x4(uint32_t* r, uint32_t addr) {
    asm volatile("ldmatrix.sync.aligned.m8n8.x4.shared.b16 {%0,%1,%2,%3}, [%4];"
                 : "=r"(r[0]), "=r"(r[1]), "=r"(r[2]), "=r"(r[3]) : "r"(addr));
}
__device__ __forceinline__ void mma16816(float* c, const uint32_t* a,
                                         const uint32_t* b) {
    asm volatile(
        "mma.sync.aligned.m16n8k16.row.col.f32.f16.f16.f32 "
        "{%0,%1,%2,%3}, {%4,%5,%6,%7}, {%8,%9}, {%0,%1,%2,%3};"
        : "+f"(c[0]), "+f"(c[1]), "+f"(c[2]), "+f"(c[3])
        : "r"(a[0]), "r"(a[1]), "r"(a[2]), "r"(a[3]), "r"(b[0]), "r"(b[1]));
}

__device__ __forceinline__ uint32_t pkh(float a, float b) {
    __half2 t = __floats2half2_rn(a, b);
    return *(uint32_t*)&t;
}

// ---------------- scan helper ----------------------------------------------
__device__ __forceinline__ int block_scan_incl(int v) {
    __shared__ int ws[32];
    int lane = threadIdx.x & 31, wid = threadIdx.x >> 5;
#pragma unroll
    for (int o = 1; o < 32; o <<= 1) {
        int n = __shfl_up_sync(0xffffffffu, v, o);
        if (lane >= o) v += n;
    }
    if (lane == 31) ws[wid] = v;
    __syncthreads();
    int nw = blockDim.x >> 5;
    if (wid == 0) {
        int s = (lane < nw) ? ws[lane] : 0;
#pragma unroll
        for (int o = 1; o < 32; o <<= 1) {
            int n = __shfl_up_sync(0xffffffffu, s, o);
            if (lane >= o) s += n;
        }
        ws[lane] = s;
    }
    __syncthreads();
    if (wid > 0) v += ws[wid - 1];
    return v;
}

// ---------------- fused prep1: hist | x-split | prepB1 | prepB2 -------------
// blocks [0,1563): hist; [1563,2587): split; [2587,2715): prepB1;
// [2715,2971): prepB2.  g_deg zeroed by previous run's k_fc.
__global__ void __launch_bounds__(256) k_prep1(
    const int* __restrict__ dst, const float* __restrict__ X,
    __half* __restrict__ Shi,
    const float* __restrict__ W1l, const float* __restrict__ W1r,
    __half* __restrict__ Bh1,
    const float* __restrict__ W2l, const float* __restrict__ W2r,
    __half* __restrict__ Bh2) {
    int b = blockIdx.x, t = threadIdx.x;
    if (b < 1563) {
        int e4 = b * 256 + t;
        if (e4 * 4 < NE) {
            int4 d = __ldg((const int4*)dst + e4);
            atomicAdd(&g_deg[d.x], 1);
            atomicAdd(&g_deg[d.y], 1);
            atomicAdd(&g_deg[d.z], 1);
            atomicAdd(&g_deg[d.w], 1);
        }
    } else if (b < 2587) {
        const int total4 = NN * DIN / 4;
        for (int i = (b - 1563) * 256 + t; i < total4; i += 1024 * 256) {
            float4 v = ((const float4*)X)[i];
            uint2 h = make_uint2(pkh(v.x, v.y), pkh(v.z, v.w));
            *(uint2*)((char*)Shi + (size_t)i * 8) = h;
        }
    } else if (b < 2715) {
        int idx = (b - 2587) * 256 + t;          // 128 blocks -> DIN*256
        int k = idx >> 8, n = idx & 255;
        const int LDB = 2 * DIN;
        Bh1[(size_t)n * LDB + k]       = __float2half_rn(W1l[idx]);
        Bh1[(size_t)n * LDB + DIN + k] = __float2half_rn(W1r[idx]);
    } else {
        int idx = (b - 2715) * 256 + t;          // 256 blocks -> DH*256
        int k = idx >> 8, n = idx & 255;
        const int LDB = 2 * DH;
        Bh2[(size_t)n * LDB + k]      = __float2half_rn(W2l[idx]);
        Bh2[(size_t)n * LDB + DH + k] = __float2half_rn(W2r[idx]);
    }
}

// ---------------- CSR scan + fill ------------------------------------------
__global__ void k_scan1() {
    int i = blockIdx.x * 1024 + threadIdx.x;
    int v = (i < NN) ? g_deg[i] : 0;
    int incl = block_scan_incl(v);
    if (i < NN) g_rowptr[i + 1] = incl;
    if (threadIdx.x == 1023) g_bsum[blockIdx.x] = incl;
}
__global__ void k_scan3(int nb) {
    __shared__ int s_off;
    int t = threadIdx.x;
    int v = (t < nb) ? g_bsum[t] : 0;
    int incl = block_scan_incl(v);
    if (blockIdx.x == 0) {
        if (t == 0) s_off = 0;
    } else if (t == (int)blockIdx.x - 1) {
        s_off = incl;
    }
    __syncthreads();
    int i = blockIdx.x * 1024 + t;
    if (i < NN) g_rowptr[i + 1] += s_off;
    if (i == 0) g_rowptr[0] = 0;
}
__global__ void k_fill(const int* __restrict__ src, const int* __restrict__ dst) {
    int e4 = blockIdx.x * blockDim.x + threadIdx.x;
    if (e4 * 4 < NE) {
        int4 d = __ldg((const int4*)dst + e4);
        int4 s = __ldg((const int4*)src + e4);
        int p;
        p = atomicAdd(&g_cursor[d.x], 1); g_csr[g_rowptr[d.x] + p] = s.x;
        p = atomicAdd(&g_cursor[d.y], 1); g_csr[g_rowptr[d.y] + p] = s.y;
        p = atomicAdd(&g_cursor[d.z], 1); g_csr[g_rowptr[d.z] + p] = s.z;
        p = atomicAdd(&g_cursor[d.w], 1); g_csr[g_rowptr[d.w] + p] = s.w;
    }
}

// ---------------- SpMM layer1: gather fp16 table (D=128) -------------------
__global__ void __launch_bounds__(256) k_spmm1(const __half* __restrict__ Xh,
                                               __half* __restrict__ Ahi) {
    int warp = threadIdx.x >> 5, lane = threadIdx.x & 31;
    int node = blockIdx.x * 8 + warp;
    if (node >= NN) return;
    int beg = g_rowptr[node], end = g_rowptr[node + 1];
    int deg = end - beg;
    int myidx = (beg + lane < end) ? __ldg(&g_csr[beg + lane]) : 0;
    int dmax = deg < 32 ? deg : 32;

    float4 p = make_float4(0.f, 0.f, 0.f, 0.f);
    float4 q = make_float4(0.f, 0.f, 0.f, 0.f);

    auto addu2 = [&](float4& a, uint2 u) {
        __half2* ph = (__half2*)&u;
        float2 f0 = __half22float2(ph[0]);
        float2 f1 = __half22float2(ph[1]);
        a.x += f0.x; a.y += f0.y; a.z += f1.x; a.w += f1.y;
    };

    int j = 0;
    for (; j + 4 <= dmax; j += 4) {
        int s0 = __shfl_sync(0xffffffffu, myidx, j + 0);
        int s1 = __shfl_sync(0xffffffffu, myidx, j + 1);
        int s2 = __shfl_sync(0xffffffffu, myidx, j + 2);
        int s3 = __shfl_sync(0xffffffffu, myidx, j + 3);
        uint2 u0 = __ldg((const uint2*)(Xh + (size_t)s0 * DIN) + lane);
        uint2 u1 = __ldg((const uint2*)(Xh + (size_t)s1 * DIN) + lane);
        uint2 u2 = __ldg((const uint2*)(Xh + (size_t)s2 * DIN) + lane);
        uint2 u3 = __ldg((const uint2*)(Xh + (size_t)s3 * DIN) + lane);
        addu2(p, u0); addu2(q, u1); addu2(p, u2); addu2(q, u3);
    }
    for (; j < dmax; j++) {
        int s0 = __shfl_sync(0xffffffffu, myidx, j);
        addu2(p, __ldg((const uint2*)(Xh + (size_t)s0 * DIN) + lane));
    }
    for (int jj = beg + 32; jj < end; jj++) {
        int s0 = __ldg(&g_csr[jj]);
        addu2(p, __ldg((const uint2*)(Xh + (size_t)s0 * DIN) + lane));
    }

    float inv = 1.f / fmaxf((float)deg, 1.f);
    float4 a = make_float4((p.x + q.x) * inv, (p.y + q.y) * inv,
                           (p.z + q.z) * inv, (p.w + q.w) * inv);
    uint2 h = make_uint2(pkh(a.x, a.y), pkh(a.z, a.w));
    *(uint2*)(Ahi + (size_t)node * DIN + lane * 4) = h;
}

// ---------------- SpMM layer2: gather fp16 table (D=256) -------------------
__global__ void __launch_bounds__(256) k_spmm2(const __half* __restrict__ Xh,
                                               __half* __restrict__ Ahi) {
    int warp = threadIdx.x >> 5, lane = threadIdx.x & 31;
    int node = blockIdx.x * 8 + warp;
    if (node >= NN) return;
    int beg = g_rowptr[node], end = g_rowptr[node + 1];
    int deg = end - beg;
    int myidx = (beg + lane < end) ? __ldg(&g_csr[beg + lane]) : 0;
    int dmax = deg < 32 ? deg : 32;

    float p[8] = {0, 0, 0, 0, 0, 0, 0, 0};
    float q[8] = {0, 0, 0, 0, 0, 0, 0, 0};

    auto addu4 = [&](float* a, uint4 u) {
        __half2* ph = (__half2*)&u;
#pragma unroll
        for (int z = 0; z < 4; z++) {
            float2 f = __half22float2(ph[z]);
            a[z * 2] += f.x; a[z * 2 + 1] += f.y;
        }
    };

    int j = 0;
    for (; j + 2 <= dmax; j += 2) {
        int s0 = __shfl_sync(0xffffffffu, myidx, j + 0);
        int s1 = __shfl_sync(0xffffffffu, myidx, j + 1);
        uint4 u0 = __ldg((const uint4*)(Xh + (size_t)s0 * DH) + lane);
        uint4 u1 = __ldg((const uint4*)(Xh + (size_t)s1 * DH) + lane);
        addu4(p, u0); addu4(q, u1);
    }
    for (; j < dmax; j++) {
        int s0 = __shfl_sync(0xffffffffu, myidx, j);
        addu4(p, __ldg((const uint4*)(Xh + (size_t)s0 * DH) + lane));
    }
    for (int jj = beg + 32; jj < end; jj++) {
        int s0 = __ldg(&g_csr[jj]);
        addu4(p, __ldg((const uint4*)(Xh + (size_t)s0 * DH) + lane));
    }

    float inv = 1.f / fmaxf((float)deg, 1.f);
    uint4 h;
    uint32_t* hp = (uint32_t*)&h;
#pragma unroll
    for (int z = 0; z < 4; z++) {
        float v0 = (p[z * 2] + q[z * 2]) * inv;
        float v1 = (p[z * 2 + 1] + q[z * 2 + 1]) * inv;
        hp[z] = pkh(v0, v1);
    }
    *(uint4*)(Ahi + (size_t)node * DH + lane * 8) = h;
}

// ---------------- mma.sync GEMM fp16, K-chunk 64, fp16 output ---------------
// CTA 128x128, 3 stages x 32KB. acc += aH*bH. BN stats fused in epilogue.
// Out stored as fp16 (stats computed from fp32 registers, unaffected).
template <int K>
__global__ void __launch_bounds__(256, 2)
k_mmagemm(const __half* __restrict__ Ahi, const __half* __restrict__ Shi,
          const __half* __restrict__ Bh,  const float* __restrict__ bias,
          __half* __restrict__ Out, float* __restrict__ stats) {
    constexpr int CH  = 2 * K / 64;
    constexpr int LDB = 2 * K;
    constexpr int T_BH = 16384;
    constexpr int STAGE = 32768;

    extern __shared__ __align__(128) char dsm[];
    float* sbias = (float*)dsm;                 // 512B
    float* s_red = (float*)(dsm + 512);         // 1KB: sum[128], sq[128]
    uint32_t stage0 = smem_u32(dsm) + 2048;

    const int t = threadIdx.x;
    const int wid = t >> 5, lane = t & 31;
    const int wm = wid >> 2, wn = wid & 3;       // warps 2 x 4
    const int m0 = blockIdx.x * 128;
    const int n0 = blockIdx.y * 128;

    if (t < 128) { sbias[t] = bias[n0 + t]; s_red[t] = 0.f; s_red[128 + t] = 0.f; }

    float acc[4][4][4];
#pragma unroll
    for (int i = 0; i < 4; i++)
#pragma unroll
        for (int j = 0; j < 4; j++)
#pragma unroll
            for (int q = 0; q < 4; q++) acc[i][j][q] = 0.f;

    auto load_chunk = [&](int c, int s) {
        uint32_t sb = stage0 + s * STAGE;
        const __half* Ah; int k0;
        if (c < K / 64) { Ah = Ahi; k0 = c * 64; }
        else            { Ah = Shi; k0 = (c - K / 64) * 64; }
#pragma unroll
        for (int it = 0; it < 4; it++) {
            int i = t + 256 * it;                 // 0..1023
            int row = i >> 3, ch = i & 7;
            uint32_t sw = row * 128 + ((ch ^ (row & 7)) << 4);
            int gr = m0 + row; if (gr > NN - 1) gr = NN - 1;
            cpasync16(sb + sw, Ah + (size_t)gr * K + k0 + ch * 8);
            cpasync16(sb + T_BH + sw, Bh + (size_t)(n0 + row) * LDB + c * 64 + ch * 8);
        }
        CP_COMMIT();
    };

    load_chunk(0, 0);
    load_chunk(1, 1);
    if (CH > 2) load_chunk(2, 2);

#pragma unroll 1
    for (int c = 0; c < CH; c++) {
        int s = c % 3;
        int rem = CH - 1 - c;
        if (rem >= 2)      asm volatile("cp.async.wait_group 2;" ::: "memory");
        else if (rem == 1) asm volatile("cp.async.wait_group 1;" ::: "memory");
        else               asm volatile("cp.async.wait_group 0;" ::: "memory");
        __syncthreads();

        uint32_t sb = stage0 + s * STAGE;
#pragma unroll
        for (int ks = 0; ks < 4; ks++) {
            uint32_t aH[4][4], bH[4][2];
#pragma unroll
            for (int mt = 0; mt < 4; mt++) {
                int r = wm * 64 + mt * 16 + (lane & 15);
                int kc = ks * 2 + (lane >> 4);
                ldsm_x4(aH[mt], sb + r * 128 + ((kc ^ (r & 7)) << 4));
            }
#pragma unroll
            for (int np = 0; np < 2; np++) {
                int nrow = wn * 32 + np * 16 + (lane & 7) + ((lane >> 4) << 3);
                int kc = ks * 2 + ((lane >> 3) & 1);
                uint32_t bp[4];
                ldsm_x4(bp, sb + T_BH + nrow * 128 + ((kc ^ (nrow & 7)) << 4));
                bH[np * 2][0] = bp[0];     bH[np * 2][1] = bp[1];
                bH[np * 2 + 1][0] = bp[2]; bH[np * 2 + 1][1] = bp[3];
            }
#pragma unroll
            for (int mt = 0; mt < 4; mt++)
#pragma unroll
                for (int nt = 0; nt < 4; nt++)
                    mma16816(acc[mt][nt], aH[mt], bH[nt]);
        }
        __syncthreads();
        if (c + 3 < CH) load_chunk(c + 3, s);
    }

    // epilogue: bias + fp16 store + per-column BN partial stats (shfl-reduced)
    float csum[4][2], csq[4][2];
#pragma unroll
    for (int nt = 0; nt < 4; nt++) {
        csum[nt][0] = 0.f; csum[nt][1] = 0.f;
        csq[nt][0] = 0.f;  csq[nt][1] = 0.f;
    }
#pragma unroll
    for (int mt = 0; mt < 4; mt++) {
        int r0 = m0 + wm * 64 + mt * 16 + (lane >> 2);
        bool v0ok = r0 < NN, v1ok = (r0 + 8) < NN;
#pragma unroll
        for (int nt = 0; nt < 4; nt++) {
            int lc = wn * 32 + nt * 8 + (lane & 3) * 2;
            float bx = sbias[lc], by = sbias[lc + 1];
            if (v0ok) {
                float vx = acc[mt][nt][0] + bx, vy = acc[mt][nt][1] + by;
                *(uint32_t*)(Out + (size_t)r0 * DH + n0 + lc) = pkh(vx, vy);
                csum[nt][0] += vx; csq[nt][0] += vx * vx;
                csum[nt][1] += vy; csq[nt][1] += vy * vy;
            }
            if (v1ok) {
                float vx = acc[mt][nt][2] + bx, vy = acc[mt][nt][3] + by;
                *(uint32_t*)(Out + (size_t)(r0 + 8) * DH + n0 + lc) = pkh(vx, vy);
                csum[nt][0] += vx; csq[nt][0] += vx * vx;
                csum[nt][1] += vy; csq[nt][1] += vy * vy;
            }
        }
    }
#pragma unroll
    for (int nt = 0; nt < 4; nt++) {
#pragma unroll
        for (int off = 4; off < 32; off <<= 1) {
            csum[nt][0] += __shfl_xor_sync(0xffffffffu, csum[nt][0], off);
            csum[nt][1] += __shfl_xor_sync(0xffffffffu, csum[nt][1], off);
            csq[nt][0]  += __shfl_xor_sync(0xffffffffu, csq[nt][0], off);
            csq[nt][1]  += __shfl_xor_sync(0xffffffffu, csq[nt][1], off);
        }
    }
    __syncthreads();
    if (lane < 4) {
#pragma unroll
        for (int nt = 0; nt < 4; nt++) {
            int lc = wn * 32 + nt * 8 + lane * 2;
            atomicAdd(&s_red[lc], csum[nt][0]);
            atomicAdd(&s_red[lc + 1], csum[nt][1]);
            atomicAdd(&s_red[128 + lc], csq[nt][0]);
            atomicAdd(&s_red[128 + lc + 1], csq[nt][1]);
        }
    }
    __syncthreads();
    if (t < 128) {
        atomicAdd(&stats[n0 + t], s_red[t]);
        atomicAdd(&stats[256 + n0 + t], s_red[128 + t]);
    }
}

// ---------------- prep2: BN+ReLU (fp16 in) -> fp16 table + zero stats2 ------
// blocks [0,1024): bnrelu; block 1024: zero stats[512:1024) for gemm2.
__global__ void __launch_bounds__(256) k_prep2(const __half* __restrict__ H,
                                               const float* __restrict__ stats,
                                               const float* __restrict__ gam,
                                               const float* __restrict__ bet,
                                               __half* __restrict__ Hi,
                                               float* __restrict__ stats_mut) {
    int b = blockIdx.x, t = threadIdx.x;
    if (b >= 1024) {
        stats_mut[512 + t] = 0.f;
        stats_mut[768 + t] = 0.f;
        return;
    }
    __shared__ float sbn[512];
    {
        int c = t;
        float mu  = stats[c] * (1.f / NN);
        float var = stats[256 + c] * (1.f / NN) - mu * mu;
        float rstd = rsqrtf(var + 1e-5f);
        float sc = rstd * gam[c];
        sbn[c] = sc;
        sbn[256 + c] = bet[c] - mu * sc;
    }
    __syncthreads();
    const int total = NN * DH / 4;
    for (int i = b * 256 + t; i < total; i += 1024 * 256) {
        uint2 u = ((const uint2*)H)[i];
        __half2* ph = (__half2*)&u;
        float2 f0 = __half22float2(ph[0]);
        float2 f1 = __half22float2(ph[1]);
        int c = (i & 63) * 4;
        float vx = fmaxf(0.f, f0.x * sbn[c + 0] + sbn[256 + c + 0]);
        float vy = fmaxf(0.f, f0.y * sbn[c + 1] + sbn[256 + c + 1]);
        float vz = fmaxf(0.f, f1.x * sbn[c + 2] + sbn[256 + c + 2]);
        float vw = fmaxf(0.f, f1.y * sbn[c + 3] + sbn[256 + c + 3]);
        uint2 h = make_uint2(pkh(vx, vy), pkh(vz, vw));
        *(uint2*)((char*)Hi + (size_t)i * 8) = h;
    }
}

// ---------------- final FC (fp16 in, BN fused) + re-zero state --------------
// blocks [0,3125): fc; [3125,3516): zero g_deg/g_cursor + stats[0:512)
__global__ void __launch_bounds__(256) k_fc(const __half* __restrict__ H,
                                            float* __restrict__ stats,
                                            const float* __restrict__ gam,
                                            const float* __restrict__ bet,
                                            const float* __restrict__ W,
                                            const float* __restrict__ b,
                                            float* __restrict__ out) {
    int blk = blockIdx.x, t = threadIdx.x;
    if (blk >= 3125) {
        int i = (blk - 3125) * 256 + t;
        if (i < NN) { g_deg[i] = 0; g_cursor[i] = 0; }
        if (i < 512) stats[i] = 0.f;
        return;
    }
    __shared__ __align__(16) float Ws[DH * NCLS];
    __shared__ float sbn[512];
    for (int i = t; i < DH * NCLS / 4; i += 256)
        ((float4*)Ws)[i] = ((const float4*)W)[i];
    {
        int c = t;
        float mu  = stats[512 + c] * (1.f / NN);
        float var = stats[768 + c] * (1.f / NN) - mu * mu;
        float rstd = rsqrtf(var + 1e-5f);
        float sc = rstd * gam[c];
        sbn[c] = sc;
        sbn[256 + c] = bet[c] - mu * sc;
    }
    __syncthreads();
    int row = blk * 32 + (t >> 3);
    int c = (t & 7) * 4;
    if (row >= NN) return;
    const uint2* hr = (const uint2*)(H + (size_t)row * DH);
    float4 acc = *(const float4*)(b + c);
#pragma unroll 8
    for (int k4 = 0; k4 < DH / 4; k4++) {
        uint2 u = hr[k4];
        __half2* ph = (__half2*)&u;
        float2 f0 = __half22float2(ph[0]);
        float2 f1 = __half22float2(ph[1]);
        int kb = k4 * 4;
        float hx = fmaxf(0.f, f0.x * sbn[kb + 0] + sbn[256 + kb + 0]);
        float hy = fmaxf(0.f, f0.y * sbn[kb + 1] + sbn[256 + kb + 1]);
        float hz = fmaxf(0.f, f1.x * sbn[kb + 2] + sbn[256 + kb + 2]);
        float hw = fmaxf(0.f, f1.y * sbn[kb + 3] + sbn[256 + kb + 3]);
        float4 w0 = *(float4*)&Ws[(kb + 0) * NCLS + c];
        float4 w1 = *(float4*)&Ws[(kb + 1) * NCLS + c];
        float4 w2 = *(float4*)&Ws[(kb + 2) * NCLS + c];
        float4 w3 = *(float4*)&Ws[(kb + 3) * NCLS + c];
        acc.x += hx * w0.x + hy * w1.x + hz * w2.x + hw * w3.x;
        acc.y += hx * w0.y + hy * w1.y + hz * w2.y + hw * w3.y;
        acc.z += hx * w0.z + hy * w1.z + hz * w2.z + hw * w3.z;
        acc.w += hx * w0.w + hy * w1.w + hz * w2.w + hw * w3.w;
    }
    *(float4*)(out + (size_t)row * NCLS + c) = acc;
}

// ---------------- launch ----------------------------------------------------
extern "C" void kernel_launch(void* const* d_in, const int* in_sizes, int n_in,
                              void* d_out, int out_size) {
    const float* x    = (const float*)d_in[0];
    const int*   esrc = (const int*)d_in[1];
    const int*   edst = (const int*)d_in[2];
    const float* W1l  = (const float*)d_in[3];
    const float* b1   = (const float*)d_in[4];
    const float* W1r  = (const float*)d_in[5];
    const float* g1   = (const float*)d_in[6];
    const float* be1  = (const float*)d_in[7];
    const float* W2l  = (const float*)d_in[8];
    const float* b2   = (const float*)d_in[9];
    const float* W2r  = (const float*)d_in[10];
    const float* g2   = (const float*)d_in[11];
    const float* be2  = (const float*)d_in[12];
    const float* Wfc  = (const float*)d_in[13];
    const float* bfc  = (const float*)d_in[14];
    float* out = (float*)d_out;

    __half *p_Ahi, *p_Shi, *p_Bh, *p_Bh2, *p_h1, *p_h2;
    float *p_stats;
    cudaGetSymbolAddress((void**)&p_Ahi,   g_Ahi);
    cudaGetSymbolAddress((void**)&p_Shi,   g_Shi);
    cudaGetSymbolAddress((void**)&p_Bh,    g_Bhi);
    cudaGetSymbolAddress((void**)&p_Bh2,   g_Bhi2);
    cudaGetSymbolAddress((void**)&p_h1,    g_h1);
    cudaGetSymbolAddress((void**)&p_h2,    g_h2);
    cudaGetSymbolAddress((void**)&p_stats, g_stats);

    const int SMEM = 2048 + 3 * 32768;   // 100352
    cudaFuncSetAttribute(k_mmagemm<DIN>,
                         cudaFuncAttributeMaxDynamicSharedMemorySize, SMEM);
    cudaFuncSetAttribute(k_mmagemm<DH>,
                         cudaFuncAttributeMaxDynamicSharedMemorySize, SMEM);

    const int nb1 = (NN + 1023) / 1024;
    const int e4grid = (NE / 4 + 255) / 256;
    dim3 gg((NN + 127) / 128, 2);        // 782 x 2 CTAs

    // hist | split | prepB1 | prepB2 concurrent, then CSR scan + fill
    k_prep1<<<2971, 256>>>(edst, x, p_Shi, W1l, W1r, p_Bh, W2l, W2r, p_Bh2);
    k_scan1<<<nb1, 1024>>>();
    k_scan3<<<nb1, 1024>>>(nb1);
    k_fill<<<e4grid, 256>>>(esrc, edst);

    // layer 1
    k_spmm1<<<(NN + 7) / 8, 256>>>(p_Shi, p_Ahi);
    k_mmagemm<DIN><<<gg, 256, SMEM>>>(p_Ahi, p_Shi, p_Bh, b1, p_h1, p_stats);

    // bnrelu (+ zero layer2 stats)
    k_prep2<<<1025, 256>>>(p_h1, p_stats, g1, be1, p_Shi, p_stats);

    // layer 2
    k_spmm2<<<(NN + 7) / 8, 256>>>(p_Shi, p_Ahi);
    k_mmagemm<DH><<<gg, 256, SMEM>>>(p_Ahi, p_Shi, p_Bh2, b2, p_h2, p_stats + 512);

    // classifier + re-zero deg/cursor/layer1-stats for next replay
    k_fc<<<3516, 256>>>(p_h2, p_stats, g2, be2, Wfc, bfc, out);
}

// round 15
// speedup vs baseline: 1.2868x; 1.0054x over previous
#include <cuda_runtime.h>
#include <cuda_fp16.h>
#include <cstdint>

#define NN   100000
#define NE   1600000
#define DIN  128
#define DH   256
#define NCLS 32

typedef unsigned long long ull;

// ---------------- scratch (device globals; zero-init at load) ---------------
// g_deg/g_stats are re-zeroed by tail kernels each run so the next graph
// replay sees clean state (zero-init covers the first run).
__device__ int   g_deg[NN];
__device__ int   g_rowptr[NN + 1];
__device__ int   g_pos[NE];          // per-edge slot within its dst row
__device__ int   g_csr[NE];
__device__ int   g_bsum[128];
__device__ __align__(128) __half g_Ahi[(size_t)NN * DH];
__device__ __align__(128) __half g_Shi[(size_t)NN * DH];
__device__ __align__(128) __half g_Bhi[DIN * 2 * DH];    // layer1 B: 256 x 256
__device__ __align__(128) __half g_Bhi2[DH * 2 * DH];    // layer2 B: 256 x 512
__device__ __align__(128) __half g_h1[(size_t)NN * DH];  // fp16 hidden states
__device__ __align__(128) __half g_h2[(size_t)NN * DH];
__device__ float g_stats[1024];

// ---------------- helpers ---------------------------------------------------
__device__ __forceinline__ uint32_t smem_u32(const void* p) {
    uint32_t a;
    asm("{ .reg .u64 t; cvta.to.shared.u64 t, %1; cvt.u32.u64 %0, t; }"
        : "=r"(a) : "l"(p));
    return a;
}
__device__ __forceinline__ void cpasync16(uint32_t dst, const void* src) {
    asm volatile("cp.async.cg.shared.global [%0], [%1], 16;"
                 :: "r"(dst), "l"(src));
}
#define CP_COMMIT() asm volatile("cp.async.commit_group;" ::: "memory")

__device__ __forceinline__ void ldsm_x4(uint32_t* r, uint32_t addr) {
    asm volatile("ldmatrix.sync.aligned.m8n8.x4.shared.b16 {%0,%1,%2,%3}, [%4];"
                 : "=r"(r[0]), "=r"(r[1]), "=r"(r[2]), "=r"(r[3]) : "r"(addr));
}
__device__ __forceinline__ void mma16816(float* c, const uint32_t* a,
                                         const uint32_t* b) {
    asm volatile(
        "mma.sync.aligned.m16n8k16.row.col.f32.f16.f16.f32 "
        "{%0,%1,%2,%3}, {%4,%5,%6,%7}, {%8,%9}, {%0,%1,%2,%3};"
        : "+f"(c[0]), "+f"(c[1]), "+f"(c[2]), "+f"(c[3])
        : "r"(a[0]), "r"(a[1]), "r"(a[2]), "r"(a[3]), "r"(b[0]), "r"(b[1]));
}

__device__ __forceinline__ uint32_t pkh(float a, float b) {
    __half2 t = __floats2half2_rn(a, b);
    return *(uint32_t*)&t;
}

// ---------------- scan helper ----------------------------------------------
__device__ __forceinline__ int block_scan_incl(int v) {
    __shared__ int ws[32];
    int lane = threadIdx.x & 31, wid = threadIdx.x >> 5;
#pragma unroll
    for (int o = 1; o < 32; o <<= 1) {
        int n = __shfl_up_sync(0xffffffffu, v, o);
        if (lane >= o) v += n;
    }
    if (lane == 31) ws[wid] = v;
    __syncthreads();
    int nw = blockDim.x >> 5;
    if (wid == 0) {
        int s = (lane < nw) ? ws[lane] : 0;
#pragma unroll
        for (int o = 1; o < 32; o <<= 1) {
            int n = __shfl_up_sync(0xffffffffu, s, o);
            if (lane >= o) s += n;
        }
        ws[lane] = s;
    }
    __syncthreads();
    if (wid > 0) v += ws[wid - 1];
    return v;
}

// ---------------- fused prep1: hist(+pos) | x-split | prepB1 | prepB2 -------
// blocks [0,1563): hist writes per-edge slot to g_pos; [1563,2587): split;
// [2587,2715): prepB1; [2715,2971): prepB2.  g_deg zeroed by prev run's k_fc.
__global__ void __launch_bounds__(256) k_prep1(
    const int* __restrict__ dst, const float* __restrict__ X,
    __half* __restrict__ Shi,
    const float* __restrict__ W1l, const float* __restrict__ W1r,
    __half* __restrict__ Bh1,
    const float* __restrict__ W2l, const float* __restrict__ W2r,
    __half* __restrict__ Bh2) {
    int b = blockIdx.x, t = threadIdx.x;
    if (b < 1563) {
        int e4 = b * 256 + t;
        if (e4 * 4 < NE) {
            int4 d = __ldg((const int4*)dst + e4);
            int4 p;
            p.x = atomicAdd(&g_deg[d.x], 1);
            p.y = atomicAdd(&g_deg[d.y], 1);
            p.z = atomicAdd(&g_deg[d.z], 1);
            p.w = atomicAdd(&g_deg[d.w], 1);
            *((int4*)g_pos + e4) = p;
        }
    } else if (b < 2587) {
        const int total4 = NN * DIN / 4;
        for (int i = (b - 1563) * 256 + t; i < total4; i += 1024 * 256) {
            float4 v = ((const float4*)X)[i];
            uint2 h = make_uint2(pkh(v.x, v.y), pkh(v.z, v.w));
            *(uint2*)((char*)Shi + (size_t)i * 8) = h;
        }
    } else if (b < 2715) {
        int idx = (b - 2587) * 256 + t;          // 128 blocks -> DIN*256
        int k = idx >> 8, n = idx & 255;
        const int LDB = 2 * DIN;
        Bh1[(size_t)n * LDB + k]       = __float2half_rn(W1l[idx]);
        Bh1[(size_t)n * LDB + DIN + k] = __float2half_rn(W1r[idx]);
    } else {
        int idx = (b - 2715) * 256 + t;          // 256 blocks -> DH*256
        int k = idx >> 8, n = idx & 255;
        const int LDB = 2 * DH;
        Bh2[(size_t)n * LDB + k]      = __float2half_rn(W2l[idx]);
        Bh2[(size_t)n * LDB + DH + k] = __float2half_rn(W2r[idx]);
    }
}

// ---------------- CSR scan + atomic-free fill -------------------------------
__global__ void k_scan1() {
    int i = blockIdx.x * 1024 + threadIdx.x;
    int v = (i < NN) ? g_deg[i] : 0;
    int incl = block_scan_incl(v);
    if (i < NN) g_rowptr[i + 1] = incl;
    if (threadIdx.x == 1023) g_bsum[blockIdx.x] = incl;
}
__global__ void k_scan3(int nb) {
    __shared__ int s_off;
    int t = threadIdx.x;
    int v = (t < nb) ? g_bsum[t] : 0;
    int incl = block_scan_incl(v);
    if (blockIdx.x == 0) {
        if (t == 0) s_off = 0;
    } else if (t == (int)blockIdx.x - 1) {
        s_off = incl;
    }
    __syncthreads();
    int i = blockIdx.x * 1024 + t;
    if (i < NN) g_rowptr[i + 1] += s_off;
    if (i == 0) g_rowptr[0] = 0;
}
// no atomics: slot precomputed in hist
__global__ void k_fill(const int* __restrict__ src, const int* __restrict__ dst) {
    int e4 = blockIdx.x * blockDim.x + threadIdx.x;
    if (e4 * 4 < NE) {
        int4 d = __ldg((const int4*)dst + e4);
        int4 s = __ldg((const int4*)src + e4);
        int4 p = __ldg((const int4*)g_pos + e4);
        g_csr[__ldg(&g_rowptr[d.x]) + p.x] = s.x;
        g_csr[__ldg(&g_rowptr[d.y]) + p.y] = s.y;
        g_csr[__ldg(&g_rowptr[d.z]) + p.z] = s.z;
        g_csr[__ldg(&g_rowptr[d.w]) + p.w] = s.w;
    }
}

// ---------------- SpMM layer1: gather fp16 table (D=128) -------------------
__global__ void __launch_bounds__(256) k_spmm1(const __half* __restrict__ Xh,
                                               __half* __restrict__ Ahi) {
    int warp = threadIdx.x >> 5, lane = threadIdx.x & 31;
    int node = blockIdx.x * 8 + warp;
    if (node >= NN) return;
    int beg = g_rowptr[node], end = g_rowptr[node + 1];
    int deg = end - beg;
    int myidx = (beg + lane < end) ? __ldg(&g_csr[beg + lane]) : 0;
    int dmax = deg < 32 ? deg : 32;

    float4 p = make_float4(0.f, 0.f, 0.f, 0.f);
    float4 q = make_float4(0.f, 0.f, 0.f, 0.f);

    auto addu2 = [&](float4& a, uint2 u) {
        __half2* ph = (__half2*)&u;
        float2 f0 = __half22float2(ph[0]);
        float2 f1 = __half22float2(ph[1]);
        a.x += f0.x; a.y += f0.y; a.z += f1.x; a.w += f1.y;
    };

    int j = 0;
    for (; j + 4 <= dmax; j += 4) {
        int s0 = __shfl_sync(0xffffffffu, myidx, j + 0);
        int s1 = __shfl_sync(0xffffffffu, myidx, j + 1);
        int s2 = __shfl_sync(0xffffffffu, myidx, j + 2);
        int s3 = __shfl_sync(0xffffffffu, myidx, j + 3);
        uint2 u0 = __ldg((const uint2*)(Xh + (size_t)s0 * DIN) + lane);
        uint2 u1 = __ldg((const uint2*)(Xh + (size_t)s1 * DIN) + lane);
        uint2 u2 = __ldg((const uint2*)(Xh + (size_t)s2 * DIN) + lane);
        uint2 u3 = __ldg((const uint2*)(Xh + (size_t)s3 * DIN) + lane);
        addu2(p, u0); addu2(q, u1); addu2(p, u2); addu2(q, u3);
    }
    for (; j < dmax; j++) {
        int s0 = __shfl_sync(0xffffffffu, myidx, j);
        addu2(p, __ldg((const uint2*)(Xh + (size_t)s0 * DIN) + lane));
    }
    for (int jj = beg + 32; jj < end; jj++) {
        int s0 = __ldg(&g_csr[jj]);
        addu2(p, __ldg((const uint2*)(Xh + (size_t)s0 * DIN) + lane));
    }

    float inv = 1.f / fmaxf((float)deg, 1.f);
    float4 a = make_float4((p.x + q.x) * inv, (p.y + q.y) * inv,
                           (p.z + q.z) * inv, (p.w + q.w) * inv);
    uint2 h = make_uint2(pkh(a.x, a.y), pkh(a.z, a.w));
    *(uint2*)(Ahi + (size_t)node * DIN + lane * 4) = h;
}

// ---------------- SpMM layer2: gather fp16 table (D=256) -------------------
__global__ void __launch_bounds__(256) k_spmm2(const __half* __restrict__ Xh,
                                               __half* __restrict__ Ahi) {
    int warp = threadIdx.x >> 5, lane = threadIdx.x & 31;
    int node = blockIdx.x * 8 + warp;
    if (node >= NN) return;
    int beg = g_rowptr[node], end = g_rowptr[node + 1];
    int deg = end - beg;
    int myidx = (beg + lane < end) ? __ldg(&g_csr[beg + lane]) : 0;
    int dmax = deg < 32 ? deg : 32;

    float p[8] = {0, 0, 0, 0, 0, 0, 0, 0};
    float q[8] = {0, 0, 0, 0, 0, 0, 0, 0};

    auto addu4 = [&](float* a, uint4 u) {
        __half2* ph = (__half2*)&u;
#pragma unroll
        for (int z = 0; z < 4; z++) {
            float2 f = __half22float2(ph[z]);
            a[z * 2] += f.x; a[z * 2 + 1] += f.y;
        }
    };

    int j = 0;
    for (; j + 2 <= dmax; j += 2) {
        int s0 = __shfl_sync(0xffffffffu, myidx, j + 0);
        int s1 = __shfl_sync(0xffffffffu, myidx, j + 1);
        uint4 u0 = __ldg((const uint4*)(Xh + (size_t)s0 * DH) + lane);
        uint4 u1 = __ldg((const uint4*)(Xh + (size_t)s1 * DH) + lane);
        addu4(p, u0); addu4(q, u1);
    }
    for (; j < dmax; j++) {
        int s0 = __shfl_sync(0xffffffffu, myidx, j);
        addu4(p, __ldg((const uint4*)(Xh + (size_t)s0 * DH) + lane));
    }
    for (int jj = beg + 32; jj < end; jj++) {
        int s0 = __ldg(&g_csr[jj]);
        addu4(p, __ldg((const uint4*)(Xh + (size_t)s0 * DH) + lane));
    }

    float inv = 1.f / fmaxf((float)deg, 1.f);
    uint4 h;
    uint32_t* hp = (uint32_t*)&h;
#pragma unroll
    for (int z = 0; z < 4; z++) {
        float v0 = (p[z * 2] + q[z * 2]) * inv;
        float v1 = (p[z * 2 + 1] + q[z * 2 + 1]) * inv;
        hp[z] = pkh(v0, v1);
    }
    *(uint4*)(Ahi + (size_t)node * DH + lane * 8) = h;
}

// ---------------- mma.sync GEMM fp16, K-chunk 64, fp16 output ---------------
// CTA 128x128, 3 stages x 32KB. acc += aH*bH. BN stats fused in epilogue.
template <int K>
__global__ void __launch_bounds__(256, 2)
k_mmagemm(const __half* __restrict__ Ahi, const __half* __restrict__ Shi,
          const __half* __restrict__ Bh,  const float* __restrict__ bias,
          __half* __restrict__ Out, float* __restrict__ stats) {
    constexpr int CH  = 2 * K / 64;
    constexpr int LDB = 2 * K;
    constexpr int T_BH = 16384;
    constexpr int STAGE = 32768;

    extern __shared__ __align__(128) char dsm[];
    float* sbias = (float*)dsm;                 // 512B
    float* s_red = (float*)(dsm + 512);         // 1KB: sum[128], sq[128]
    uint32_t stage0 = smem_u32(dsm) + 2048;

    const int t = threadIdx.x;
    const int wid = t >> 5, lane = t & 31;
    const int wm = wid >> 2, wn = wid & 3;       // warps 2 x 4
    const int m0 = blockIdx.x * 128;
    const int n0 = blockIdx.y * 128;

    if (t < 128) { sbias[t] = bias[n0 + t]; s_red[t] = 0.f; s_red[128 + t] = 0.f; }

    float acc[4][4][4];
#pragma unroll
    for (int i = 0; i < 4; i++)
#pragma unroll
        for (int j = 0; j < 4; j++)
#pragma unroll
            for (int q = 0; q < 4; q++) acc[i][j][q] = 0.f;

    auto load_chunk = [&](int c, int s) {
        uint32_t sb = stage0 + s * STAGE;
        const __half* Ah; int k0;
        if (c < K / 64) { Ah = Ahi; k0 = c * 64; }
        else            { Ah = Shi; k0 = (c - K / 64) * 64; }
#pragma unroll
        for (int it = 0; it < 4; it++) {
            int i = t + 256 * it;                 // 0..1023
            int row = i >> 3, ch = i & 7;
            uint32_t sw = row * 128 + ((ch ^ (row & 7)) << 4);
            int gr = m0 + row; if (gr > NN - 1) gr = NN - 1;
            cpasync16(sb + sw, Ah + (size_t)gr * K + k0 + ch * 8);
            cpasync16(sb + T_BH + sw, Bh + (size_t)(n0 + row) * LDB + c * 64 + ch * 8);
        }
        CP_COMMIT();
    };

    load_chunk(0, 0);
    load_chunk(1, 1);
    if (CH > 2) load_chunk(2, 2);

#pragma unroll 1
    for (int c = 0; c < CH; c++) {
        int s = c % 3;
        int rem = CH - 1 - c;
        if (rem >= 2)      asm volatile("cp.async.wait_group 2;" ::: "memory");
        else if (rem == 1) asm volatile("cp.async.wait_group 1;" ::: "memory");
        else               asm volatile("cp.async.wait_group 0;" ::: "memory");
        __syncthreads();

        uint32_t sb = stage0 + s * STAGE;
#pragma unroll
        for (int ks = 0; ks < 4; ks++) {
            uint32_t aH[4][4], bH[4][2];
#pragma unroll
            for (int mt = 0; mt < 4; mt++) {
                int r = wm * 64 + mt * 16 + (lane & 15);
                int kc = ks * 2 + (lane >> 4);
                ldsm_x4(aH[mt], sb + r * 128 + ((kc ^ (r & 7)) << 4));
            }
#pragma unroll
            for (int np = 0; np < 2; np++) {
                int nrow = wn * 32 + np * 16 + (lane & 7) + ((lane >> 4) << 3);
                int kc = ks * 2 + ((lane >> 3) & 1);
                uint32_t bp[4];
                ldsm_x4(bp, sb + T_BH + nrow * 128 + ((kc ^ (nrow & 7)) << 4));
                bH[np * 2][0] = bp[0];     bH[np * 2][1] = bp[1];
                bH[np * 2 + 1][0] = bp[2]; bH[np * 2 + 1][1] = bp[3];
            }
#pragma unroll
            for (int mt = 0; mt < 4; mt++)
#pragma unroll
                for (int nt = 0; nt < 4; nt++)
                    mma16816(acc[mt][nt], aH[mt], bH[nt]);
        }
        __syncthreads();
        if (c + 3 < CH) load_chunk(c + 3, s);
    }

    // epilogue: bias + fp16 store + per-column BN partial stats (shfl-reduced)
    float csum[4][2], csq[4][2];
#pragma unroll
    for (int nt = 0; nt < 4; nt++) {
        csum[nt][0] = 0.f; csum[nt][1] = 0.f;
        csq[nt][0] = 0.f;  csq[nt][1] = 0.f;
    }
#pragma unroll
    for (int mt = 0; mt < 4; mt++) {
        int r0 = m0 + wm * 64 + mt * 16 + (lane >> 2);
        bool v0ok = r0 < NN, v1ok = (r0 + 8) < NN;
#pragma unroll
        for (int nt = 0; nt < 4; nt++) {
            int lc = wn * 32 + nt * 8 + (lane & 3) * 2;
            float bx = sbias[lc], by = sbias[lc + 1];
            if (v0ok) {
                float vx = acc[mt][nt][0] + bx, vy = acc[mt][nt][1] + by;
                *(uint32_t*)(Out + (size_t)r0 * DH + n0 + lc) = pkh(vx, vy);
                csum[nt][0] += vx; csq[nt][0] += vx * vx;
                csum[nt][1] += vy; csq[nt][1] += vy * vy;
            }
            if (v1ok) {
                float vx = acc[mt][nt][2] + bx, vy = acc[mt][nt][3] + by;
                *(uint32_t*)(Out + (size_t)(r0 + 8) * DH + n0 + lc) = pkh(vx, vy);
                csum[nt][0] += vx; csq[nt][0] += vx * vx;
                csum[nt][1] += vy; csq[nt][1] += vy * vy;
            }
        }
    }
#pragma unroll
    for (int nt = 0; nt < 4; nt++) {
#pragma unroll
        for (int off = 4; off < 32; off <<= 1) {
            csum[nt][0] += __shfl_xor_sync(0xffffffffu, csum[nt][0], off);
            csum[nt][1] += __shfl_xor_sync(0xffffffffu, csum[nt][1], off);
            csq[nt][0]  += __shfl_xor_sync(0xffffffffu, csq[nt][0], off);
            csq[nt][1]  += __shfl_xor_sync(0xffffffffu, csq[nt][1], off);
        }
    }
    __syncthreads();
    if (lane < 4) {
#pragma unroll
        for (int nt = 0; nt < 4; nt++) {
            int lc = wn * 32 + nt * 8 + lane * 2;
            atomicAdd(&s_red[lc], csum[nt][0]);
            atomicAdd(&s_red[lc + 1], csum[nt][1]);
            atomicAdd(&s_red[128 + lc], csq[nt][0]);
            atomicAdd(&s_red[128 + lc + 1], csq[nt][1]);
        }
    }
    __syncthreads();
    if (t < 128) {
        atomicAdd(&stats[n0 + t], s_red[t]);
        atomicAdd(&stats[256 + n0 + t], s_red[128 + t]);
    }
}

// ---------------- prep2: BN+ReLU (fp16 in) -> fp16 table + zero stats2 ------
// blocks [0,1024): bnrelu; block 1024: zero stats[512:1024) for gemm2.
__global__ void __launch_bounds__(256) k_prep2(const __half* __restrict__ H,
                                               const float* __restrict__ stats,
                                               const float* __restrict__ gam,
                                               const float* __restrict__ bet,
                                               __half* __restrict__ Hi,
                                               float* __restrict__ stats_mut) {
    int b = blockIdx.x, t = threadIdx.x;
    if (b >= 1024) {
        stats_mut[512 + t] = 0.f;
        stats_mut[768 + t] = 0.f;
        return;
    }
    __shared__ float sbn[512];
    {
        int c = t;
        float mu  = stats[c] * (1.f / NN);
        float var = stats[256 + c] * (1.f / NN) - mu * mu;
        float rstd = rsqrtf(var + 1e-5f);
        float sc = rstd * gam[c];
        sbn[c] = sc;
        sbn[256 + c] = bet[c] - mu * sc;
    }
    __syncthreads();
    const int total = NN * DH / 4;
    for (int i = b * 256 + t; i < total; i += 1024 * 256) {
        uint2 u = ((const uint2*)H)[i];
        __half2* ph = (__half2*)&u;
        float2 f0 = __half22float2(ph[0]);
        float2 f1 = __half22float2(ph[1]);
        int c = (i & 63) * 4;
        float vx = fmaxf(0.f, f0.x * sbn[c + 0] + sbn[256 + c + 0]);
        float vy = fmaxf(0.f, f0.y * sbn[c + 1] + sbn[256 + c + 1]);
        float vz = fmaxf(0.f, f1.x * sbn[c + 2] + sbn[256 + c + 2]);
        float vw = fmaxf(0.f, f1.y * sbn[c + 3] + sbn[256 + c + 3]);
        uint2 h = make_uint2(pkh(vx, vy), pkh(vz, vw));
        *(uint2*)((char*)Hi + (size_t)i * 8) = h;
    }
}

// ---------------- final FC (fp16 in, BN fused) + re-zero state --------------
// blocks [0,3125): fc; [3125,3516): zero g_deg + stats[0:512)
__global__ void __launch_bounds__(256) k_fc(const __half* __restrict__ H,
                                            float* __restrict__ stats,
                                            const float* __restrict__ gam,
                                            const float* __restrict__ bet,
                                            const float* __restrict__ W,
                                            const float* __restrict__ b,
                                            float* __restrict__ out) {
    int blk = blockIdx.x, t = threadIdx.x;
    if (blk >= 3125) {
        int i = (blk - 3125) * 256 + t;
        if (i < NN) g_deg[i] = 0;
        if (i < 512) stats[i] = 0.f;
        return;
    }
    __shared__ __align__(16) float Ws[DH * NCLS];
    __shared__ float sbn[512];
    for (int i = t; i < DH * NCLS / 4; i += 256)
        ((float4*)Ws)[i] = ((const float4*)W)[i];
    {
        int c = t;
        float mu  = stats[512 + c] * (1.f / NN);
        float var = stats[768 + c] * (1.f / NN) - mu * mu;
        float rstd = rsqrtf(var + 1e-5f);
        float sc = rstd * gam[c];
        sbn[c] = sc;
        sbn[256 + c] = bet[c] - mu * sc;
    }
    __syncthreads();
    int row = blk * 32 + (t >> 3);
    int c = (t & 7) * 4;
    if (row >= NN) return;
    const uint2* hr = (const uint2*)(H + (size_t)row * DH);
    float4 acc = *(const float4*)(b + c);
#pragma unroll 8
    for (int k4 = 0; k4 < DH / 4; k4++) {
        uint2 u = hr[k4];
        __half2* ph = (__half2*)&u;
        float2 f0 = __half22float2(ph[0]);
        float2 f1 = __half22float2(ph[1]);
        int kb = k4 * 4;
        float hx = fmaxf(0.f, f0.x * sbn[kb + 0] + sbn[256 + kb + 0]);
        float hy = fmaxf(0.f, f0.y * sbn[kb + 1] + sbn[256 + kb + 1]);
        float hz = fmaxf(0.f, f1.x * sbn[kb + 2] + sbn[256 + kb + 2]);
        float hw = fmaxf(0.f, f1.y * sbn[kb + 3] + sbn[256 + kb + 3]);
        float4 w0 = *(float4*)&Ws[(kb + 0) * NCLS + c];
        float4 w1 = *(float4*)&Ws[(kb + 1) * NCLS + c];
        float4 w2 = *(float4*)&Ws[(kb + 2) * NCLS + c];
        float4 w3 = *(float4*)&Ws[(kb + 3) * NCLS + c];
        acc.x += hx * w0.x + hy * w1.x + hz * w2.x + hw * w3.x;
        acc.y += hx * w0.y + hy * w1.y + hz * w2.y + hw * w3.y;
        acc.z += hx * w0.z + hy * w1.z + hz * w2.z + hw * w3.z;
        acc.w += hx * w0.w + hy * w1.w + hz * w2.w + hw * w3.w;
    }
    *(float4*)(out + (size_t)row * NCLS + c) = acc;
}

// ---------------- launch ----------------------------------------------------
extern "C" void kernel_launch(void* const* d_in, const int* in_sizes, int n_in,
                              void* d_out, int out_size) {
    const float* x    = (const float*)d_in[0];
    const int*   esrc = (const int*)d_in[1];
    const int*   edst = (const int*)d_in[2];
    const float* W1l  = (const float*)d_in[3];
    const float* b1   = (const float*)d_in[4];
    const float* W1r  = (const float*)d_in[5];
    const float* g1   = (const float*)d_in[6];
    const float* be1  = (const float*)d_in[7];
    const float* W2l  = (const float*)d_in[8];
    const float* b2   = (const float*)d_in[9];
    const float* W2r  = (const float*)d_in[10];
    const float* g2   = (const float*)d_in[11];
    const float* be2  = (const float*)d_in[12];
    const float* Wfc  = (const float*)d_in[13];
    const float* bfc  = (const float*)d_in[14];
    float* out = (float*)d_out;

    __half *p_Ahi, *p_Shi, *p_Bh, *p_Bh2, *p_h1, *p_h2;
    float *p_stats;
    cudaGetSymbolAddress((void**)&p_Ahi,   g_Ahi);
    cudaGetSymbolAddress((void**)&p_Shi,   g_Shi);
    cudaGetSymbolAddress((void**)&p_Bh,    g_Bhi);
    cudaGetSymbolAddress((void**)&p_Bh2,   g_Bhi2);
    cudaGetSymbolAddress((void**)&p_h1,    g_h1);
    cudaGetSymbolAddress((void**)&p_h2,    g_h2);
    cudaGetSymbolAddress((void**)&p_stats, g_stats);

    const int SMEM = 2048 + 3 * 32768;   // 100352
    cudaFuncSetAttribute(k_mmagemm<DIN>,
                         cudaFuncAttributeMaxDynamicSharedMemorySize, SMEM);
    cudaFuncSetAttribute(k_mmagemm<DH>,
                         cudaFuncAttributeMaxDynamicSharedMemorySize, SMEM);

    const int nb1 = (NN + 1023) / 1024;
    const int e4grid = (NE / 4 + 255) / 256;
    dim3 gg((NN + 127) / 128, 2);        // 782 x 2 CTAs

    // hist(+pos) | split | prepB1 | prepB2 concurrent, then CSR scan + fill
    k_prep1<<<2971, 256>>>(edst, x, p_Shi, W1l, W1r, p_Bh, W2l, W2r, p_Bh2);
    k_scan1<<<nb1, 1024>>>();
    k_scan3<<<nb1, 1024>>>(nb1);
    k_fill<<<e4grid, 256>>>(esrc, edst);

    // layer 1
    k_spmm1<<<(NN + 7) / 8, 256>>>(p_Shi, p_Ahi);
    k_mmagemm<DIN><<<gg, 256, SMEM>>>(p_Ahi, p_Shi, p_Bh, b1, p_h1, p_stats);

    // bnrelu (+ zero layer2 stats)
    k_prep2<<<1025, 256>>>(p_h1, p_stats, g1, be1, p_Shi, p_stats);

    // layer 2
    k_spmm2<<<(NN + 7) / 8, 256>>>(p_Shi, p_Ahi);
    k_mmagemm<DH><<<gg, 256, SMEM>>>(p_Ahi, p_Shi, p_Bh2, b2, p_h2, p_stats + 512);

    // classifier + re-zero deg/layer1-stats for next replay
    k_fc<<<3516, 256>>>(p_h2, p_stats, g2, be2, Wfc, bfc, out);
}